// round 1
// baseline (speedup 1.0000x reference)
#include <cuda_runtime.h>
#include <math.h>
#include <stdint.h>

typedef unsigned long long ull;

#define NTOK 16384      // B*S
#define HD   512
#define FD   1024
#define NE   16
#define TOPK 2
#define RB   2048       // router blocks (8 tokens each)
#define NPAIR (NTOK*TOPK)

// ---------------- scratch (static device globals; no allocation) ----------------
__device__ int   g_counts[NE];
__device__ int   g_offsets[NE];
__device__ int   g_cursor[NE];
__device__ float g_blockP[RB*NE];
__device__ int   g_topk_idx[NPAIR];
__device__ float g_topk_w[NPAIR];
__device__ int   g_pair_tok[NPAIR];
__device__ float g_pair_w[NPAIR];
__device__ float g_h[(size_t)NPAIR * FD];   // 128 MiB fp32 intermediate

// ---------------- packed f32x2 helpers (full-rate fp32 on Blackwell) -------------
__device__ __forceinline__ ull pack_dup(float v) {
    ull r; asm("mov.b64 %0, {%1, %2};" : "=l"(r) : "f"(v), "f"(v)); return r;
}
__device__ __forceinline__ void fma2(ull &d, ull a, ull b) {
    asm("fma.rn.f32x2 %0, %1, %2, %0;" : "+l"(d) : "l"(a), "l"(b));
}
__device__ __forceinline__ float2 unpack2(ull v) {
    float lo, hi; asm("mov.b64 {%0, %1}, %2;" : "=f"(lo), "=f"(hi) : "l"(v));
    return make_float2(lo, hi);
}

// ---------------- init: zero per-launch counters ---------------------------------
__global__ void init_kernel() {
    if (threadIdx.x < NE) g_counts[threadIdx.x] = 0;
}

// ---------------- router: logits, top-2, softmax weights, f/P stats --------------
__global__ void __launch_bounds__(256) router_kernel(const float* __restrict__ x,
                                                     const float* __restrict__ Wr)
{
    __shared__ float sP[8][16];
    const int warp = threadIdx.x >> 5;
    const int lane = threadIdx.x & 31;
    const int t = blockIdx.x * 8 + warp;

    float acc[NE];
#pragma unroll
    for (int e = 0; e < NE; e++) acc[e] = 0.f;

    const float* xr = x + (size_t)t * HD;
    for (int i = lane; i < HD; i += 32) {
        float xv = xr[i];
#pragma unroll
        for (int e = 0; e < NE; e++) acc[e] = fmaf(xv, Wr[e*HD + i], acc[e]);
    }
#pragma unroll
    for (int e = 0; e < NE; e++) {
#pragma unroll
        for (int o = 16; o > 0; o >>= 1)
            acc[e] += __shfl_xor_sync(0xffffffffu, acc[e], o);
    }
    // every lane now holds all 16 logits; lane 0 does the scalar epilogue
    if (lane == 0) {
        float m = acc[0];
#pragma unroll
        for (int e = 1; e < NE; e++) m = fmaxf(m, acc[e]);
        float pr[NE]; float s = 0.f;
#pragma unroll
        for (int e = 0; e < NE; e++) { pr[e] = expf(acc[e] - m); s += pr[e]; }
        float inv = 1.f / s;
#pragma unroll
        for (int e = 0; e < NE; e++) sP[warp][e] = pr[e] * inv;

        int i0 = 0; float v0 = acc[0];
#pragma unroll
        for (int e = 1; e < NE; e++) if (acc[e] > v0) { v0 = acc[e]; i0 = e; }
        int i1 = (i0 == 0) ? 1 : 0; float v1 = acc[i1 == 0 ? 0 : 1];
        v1 = -3.4e38f; i1 = -1;
#pragma unroll
        for (int e = 0; e < NE; e++) if (e != i0 && acc[e] > v1) { v1 = acc[e]; i1 = e; }

        float e1 = expf(v1 - v0);
        float w0 = 1.f / (1.f + e1);
        float w1 = e1 / (1.f + e1);
        g_topk_idx[2*t]   = i0;  g_topk_idx[2*t+1] = i1;
        g_topk_w[2*t]     = w0;  g_topk_w[2*t+1]   = w1;
        atomicAdd(&g_counts[i0], 1);
        atomicAdd(&g_counts[i1], 1);
    }
    __syncthreads();
    if (threadIdx.x < NE) {
        float s = 0.f;
#pragma unroll
        for (int w = 0; w < 8; w++) s += sP[w][threadIdx.x];   // fixed order: deterministic
        g_blockP[blockIdx.x * NE + threadIdx.x] = s;
    }
}

// ---------------- finalize: offsets, cursors, l_aux ------------------------------
__global__ void finalize_kernel(float* __restrict__ out, int out_size)
{
    __shared__ float part[256];
    __shared__ float sPe[NE];
    const int t = threadIdx.x;
    const int e = t & 15, c = t >> 4;           // 16 chunks of 128 blocks
    float s = 0.f;
    for (int b = c*128; b < c*128 + 128; ++b) s += g_blockP[b*NE + e];
    part[t] = s;
    __syncthreads();
    if (t < NE) {
        float s2 = 0.f;
#pragma unroll
        for (int cc = 0; cc < 16; ++cc) s2 += part[cc*16 + t];  // fixed order
        sPe[t] = s2;
    }
    __syncthreads();
    if (t == 0) {
        int off = 0; float laux = 0.f;
#pragma unroll
        for (int ee = 0; ee < NE; ++ee) {
            g_offsets[ee] = off; g_cursor[ee] = off;
            int cnt = g_counts[ee];
            off += cnt;
            float f = (float)cnt * (1.0f / (float)(NTOK * TOPK));
            float P = sPe[ee]    * (1.0f / (float)NTOK);
            laux += f * P;
        }
        laux *= (float)NE;
        if (out_size > NTOK * HD) out[NTOK * HD] = laux;
    }
}

// ---------------- scatter tokens into per-expert compact lists -------------------
__global__ void scatter_kernel()
{
    int t = blockIdx.x * blockDim.x + threadIdx.x;
    if (t >= NTOK) return;
#pragma unroll
    for (int j = 0; j < TOPK; j++) {
        int e = g_topk_idx[2*t + j];
        int pos = atomicAdd(&g_cursor[e], 1);
        g_pair_tok[pos] = t;
        g_pair_w[pos]   = g_topk_w[2*t + j];
    }
}

// ---------------- GEMM1: h = gelu(Xg @ W1_e^T + b1_e) ---------------------------
// 128x128 tile, BK=16, 256 threads, 8x8 per thread via packed f32x2.
__global__ void __launch_bounds__(256, 2) gemm1_kernel(const float* __restrict__ x,
                                                       const float* __restrict__ W1,
                                                       const float* __restrict__ b1)
{
    const int e = blockIdx.z;
    const int count = g_counts[e];
    const int m0 = blockIdx.x * 128;
    if (m0 >= count) return;
    const int offset = g_offsets[e];
    const int n0 = blockIdx.y * 128;

    __shared__ float As[16][132];
    __shared__ float Bs[16][132];
    __shared__ int sTok[128];

    const int tid = threadIdx.x;
    if (tid < 128) {
        int m = m0 + tid;
        sTok[tid] = (m < count) ? g_pair_tok[offset + m] : g_pair_tok[offset];
    }
    __syncthreads();

    const int tx = tid & 15;        // 16 col-groups of 8
    const int ty = tid >> 4;        // 16 row-groups of 8
    const int lrow = tid >> 2;      // 0..63 (two passes: +0, +64)
    const int lk = (tid & 3) << 2;  // 0,4,8,12

    ull acc[4][8];
#pragma unroll
    for (int i = 0; i < 4; i++)
#pragma unroll
        for (int j = 0; j < 8; j++) acc[i][j] = 0ull;

    const float* aptr0 = x + (size_t)sTok[lrow]      * HD + lk;
    const float* aptr1 = x + (size_t)sTok[lrow + 64] * HD + lk;
    const float* bbase = W1 + ((size_t)e * FD + n0) * HD + lk;
    const float* bptr0 = bbase + (size_t)lrow * HD;
    const float* bptr1 = bbase + (size_t)(lrow + 64) * HD;

    float4 ra0 = *(const float4*)(aptr0);
    float4 ra1 = *(const float4*)(aptr1);
    float4 rb0 = *(const float4*)(bptr0);
    float4 rb1 = *(const float4*)(bptr1);

    for (int k0 = 0; k0 < HD; k0 += 16) {
        As[lk+0][lrow]    = ra0.x; As[lk+1][lrow]    = ra0.y; As[lk+2][lrow]    = ra0.z; As[lk+3][lrow]    = ra0.w;
        As[lk+0][lrow+64] = ra1.x; As[lk+1][lrow+64] = ra1.y; As[lk+2][lrow+64] = ra1.z; As[lk+3][lrow+64] = ra1.w;
        Bs[lk+0][lrow]    = rb0.x; Bs[lk+1][lrow]    = rb0.y; Bs[lk+2][lrow]    = rb0.z; Bs[lk+3][lrow]    = rb0.w;
        Bs[lk+0][lrow+64] = rb1.x; Bs[lk+1][lrow+64] = rb1.y; Bs[lk+2][lrow+64] = rb1.z; Bs[lk+3][lrow+64] = rb1.w;
        __syncthreads();
        int kn = k0 + 16;
        if (kn < HD) {   // prefetch next tile while computing
            ra0 = *(const float4*)(aptr0 + kn);
            ra1 = *(const float4*)(aptr1 + kn);
            rb0 = *(const float4*)(bptr0 + kn);
            rb1 = *(const float4*)(bptr1 + kn);
        }
#pragma unroll
        for (int k = 0; k < 16; k++) {
            const ull* ap = (const ull*)&As[k][ty*8];
            ull aA[4] = {ap[0], ap[1], ap[2], ap[3]};
            float4 bl = *(const float4*)&Bs[k][tx*8];
            float4 bh = *(const float4*)&Bs[k][tx*8 + 4];
            ull bD[8] = {pack_dup(bl.x), pack_dup(bl.y), pack_dup(bl.z), pack_dup(bl.w),
                         pack_dup(bh.x), pack_dup(bh.y), pack_dup(bh.z), pack_dup(bh.w)};
#pragma unroll
            for (int ip = 0; ip < 4; ip++)
#pragma unroll
                for (int j = 0; j < 8; j++) fma2(acc[ip][j], aA[ip], bD[j]);
        }
        __syncthreads();
    }

    float bias[8];
#pragma unroll
    for (int j = 0; j < 8; j++) bias[j] = b1[(size_t)e*FD + n0 + tx*8 + j];

#pragma unroll
    for (int ip = 0; ip < 4; ip++) {
        float lo[8], hi[8];
#pragma unroll
        for (int j = 0; j < 8; j++) { float2 p = unpack2(acc[ip][j]); lo[j] = p.x; hi[j] = p.y; }
#pragma unroll
        for (int half = 0; half < 2; half++) {
            int m = ty*8 + ip*2 + half;
            int gm = m0 + m;
            if (gm < count) {
                float outv[8];
#pragma unroll
                for (int j = 0; j < 8; j++) {
                    float v = ((half == 0) ? lo[j] : hi[j]) + bias[j];
                    float u = 0.7978845608028654f * (v + 0.044715f * v * v * v);
                    outv[j] = 0.5f * v * (1.0f + tanhf(u));   // jax.nn.gelu approximate=True
                }
                float* dst = g_h + (size_t)(offset + gm) * FD + n0 + tx*8;
                *(float4*)dst       = make_float4(outv[0], outv[1], outv[2], outv[3]);
                *(float4*)(dst + 4) = make_float4(outv[4], outv[5], outv[6], outv[7]);
            }
        }
    }
}

// ---------------- GEMM2: y += w * (h @ W2_e^T + b2_e) ----------------------------
__global__ void __launch_bounds__(256, 2) gemm2_kernel(const float* __restrict__ W2,
                                                       const float* __restrict__ b2,
                                                       float* __restrict__ y)
{
    const int e = blockIdx.z;
    const int count = g_counts[e];
    const int m0 = blockIdx.x * 128;
    if (m0 >= count) return;
    const int offset = g_offsets[e];
    const int n0 = blockIdx.y * 128;

    __shared__ float As[16][132];
    __shared__ float Bs[16][132];
    __shared__ int   sTok[128];
    __shared__ float sW[128];

    const int tid = threadIdx.x;
    if (tid < 128) {
        int m = m0 + tid;
        int mm = (m < count) ? m : (count - 1);
        sTok[tid] = g_pair_tok[offset + mm];
        sW[tid]   = g_pair_w[offset + mm];
    }
    __syncthreads();

    const int tx = tid & 15;
    const int ty = tid >> 4;
    const int lrow = tid >> 2;
    const int lk = (tid & 3) << 2;

    ull acc[4][8];
#pragma unroll
    for (int i = 0; i < 4; i++)
#pragma unroll
        for (int j = 0; j < 8; j++) acc[i][j] = 0ull;

    int r0 = m0 + lrow;      if (r0 >= count) r0 = count - 1;
    int r1 = m0 + lrow + 64; if (r1 >= count) r1 = count - 1;
    const float* aptr0 = g_h + (size_t)(offset + r0) * FD + lk;
    const float* aptr1 = g_h + (size_t)(offset + r1) * FD + lk;
    const float* bbase = W2 + ((size_t)e * HD + n0) * FD + lk;
    const float* bptr0 = bbase + (size_t)lrow * FD;
    const float* bptr1 = bbase + (size_t)(lrow + 64) * FD;

    float4 ra0 = *(const float4*)(aptr0);
    float4 ra1 = *(const float4*)(aptr1);
    float4 rb0 = *(const float4*)(bptr0);
    float4 rb1 = *(const float4*)(bptr1);

    for (int k0 = 0; k0 < FD; k0 += 16) {
        As[lk+0][lrow]    = ra0.x; As[lk+1][lrow]    = ra0.y; As[lk+2][lrow]    = ra0.z; As[lk+3][lrow]    = ra0.w;
        As[lk+0][lrow+64] = ra1.x; As[lk+1][lrow+64] = ra1.y; As[lk+2][lrow+64] = ra1.z; As[lk+3][lrow+64] = ra1.w;
        Bs[lk+0][lrow]    = rb0.x; Bs[lk+1][lrow]    = rb0.y; Bs[lk+2][lrow]    = rb0.z; Bs[lk+3][lrow]    = rb0.w;
        Bs[lk+0][lrow+64] = rb1.x; Bs[lk+1][lrow+64] = rb1.y; Bs[lk+2][lrow+64] = rb1.z; Bs[lk+3][lrow+64] = rb1.w;
        __syncthreads();
        int kn = k0 + 16;
        if (kn < FD) {
            ra0 = *(const float4*)(aptr0 + kn);
            ra1 = *(const float4*)(aptr1 + kn);
            rb0 = *(const float4*)(bptr0 + kn);
            rb1 = *(const float4*)(bptr1 + kn);
        }
#pragma unroll
        for (int k = 0; k < 16; k++) {
            const ull* ap = (const ull*)&As[k][ty*8];
            ull aA[4] = {ap[0], ap[1], ap[2], ap[3]};
            float4 bl = *(const float4*)&Bs[k][tx*8];
            float4 bh = *(const float4*)&Bs[k][tx*8 + 4];
            ull bD[8] = {pack_dup(bl.x), pack_dup(bl.y), pack_dup(bl.z), pack_dup(bl.w),
                         pack_dup(bh.x), pack_dup(bh.y), pack_dup(bh.z), pack_dup(bh.w)};
#pragma unroll
            for (int ip = 0; ip < 4; ip++)
#pragma unroll
                for (int j = 0; j < 8; j++) fma2(acc[ip][j], aA[ip], bD[j]);
        }
        __syncthreads();
    }

    float bias[8];
#pragma unroll
    for (int j = 0; j < 8; j++) bias[j] = b2[(size_t)e*HD + n0 + tx*8 + j];

#pragma unroll
    for (int ip = 0; ip < 4; ip++) {
        float lo[8], hi[8];
#pragma unroll
        for (int j = 0; j < 8; j++) { float2 p = unpack2(acc[ip][j]); lo[j] = p.x; hi[j] = p.y; }
#pragma unroll
        for (int half = 0; half < 2; half++) {
            int m = ty*8 + ip*2 + half;
            int gm = m0 + m;
            if (gm < count) {
                int tok = sTok[m];
                float w = sW[m];
                float* dst = y + (size_t)tok * HD + n0 + tx*8;
#pragma unroll
                for (int j = 0; j < 8; j++) {
                    float v = ((half == 0) ? lo[j] : hi[j]) + bias[j];
                    atomicAdd(&dst[j], w * v);   // exactly 2 contributions/elem: commutative => deterministic
                }
            }
        }
    }
}

// ---------------- launch ---------------------------------------------------------
extern "C" void kernel_launch(void* const* d_in, const int* in_sizes, int n_in,
                              void* d_out, int out_size)
{
    const float* x  = (const float*)d_in[0];
    const float* Wr = (const float*)d_in[1];
    const float* W1 = (const float*)d_in[2];
    const float* b1 = (const float*)d_in[3];
    const float* W2 = (const float*)d_in[4];
    const float* b2 = (const float*)d_in[5];
    float* y = (float*)d_out;

    cudaMemsetAsync(d_out, 0, (size_t)out_size * sizeof(float));
    init_kernel<<<1, 32>>>();
    router_kernel<<<RB, 256>>>(x, Wr);
    finalize_kernel<<<1, 256>>>(y, out_size);
    scatter_kernel<<<64, 256>>>();
    gemm1_kernel<<<dim3(128, FD/128, NE), 256>>>(x, W1, b1);
    gemm2_kernel<<<dim3(128, HD/128, NE), 256>>>(W2, b2, y);
}

// round 3
// speedup vs baseline: 1.6814x; 1.6814x over previous
#include <cuda_runtime.h>
#include <cuda_bf16.h>
#include <math.h>
#include <stdint.h>

typedef unsigned long long ull;

#define NTOK 16384      // B*S
#define HD   512
#define FD   1024
#define NE   16
#define TOPK 2
#define RB   2048       // router blocks (8 tokens each)
#define NPAIR (NTOK*TOPK)

// ---------------- scratch (static device globals; no allocation) ----------------
__device__ int   g_counts[NE];
__device__ int   g_offsets[NE];
__device__ int   g_cursor[NE];
__device__ float g_blockP[RB*NE];
__device__ int   g_topk_idx[NPAIR];
__device__ float g_topk_w[NPAIR];
__device__ int   g_pair_tok[NPAIR];
__device__ float g_pair_w[NPAIR];

// bf16 hi/lo split copies (x, W1, W2 all have 8388608 elements)
__device__ __nv_bfloat16 g_xhi[NTOK*HD];
__device__ __nv_bfloat16 g_xlo[NTOK*HD];
__device__ __nv_bfloat16 g_w1hi[NE*FD*HD];
__device__ __nv_bfloat16 g_w1lo[NE*FD*HD];
__device__ __nv_bfloat16 g_w2hi[NE*HD*FD];
__device__ __nv_bfloat16 g_w2lo[NE*HD*FD];
// intermediate h, stored directly as bf16 hi/lo
__device__ __nv_bfloat16 g_hhi[(size_t)NPAIR*FD];
__device__ __nv_bfloat16 g_hlo[(size_t)NPAIR*FD];

// ---------------- helpers ---------------------------------------------------------
__device__ __forceinline__ uint32_t smem_u32(const void* p) {
    uint32_t a;
    asm("{ .reg .u64 t; cvta.to.shared.u64 t, %1; cvt.u32.u64 %0, t; }" : "=r"(a) : "l"(p));
    return a;
}
__device__ __forceinline__ void cp16(uint32_t dst, const __nv_bfloat16* src) {
    asm volatile("cp.async.cg.shared.global [%0], [%1], 16;"
                 :: "r"(dst), "l"(__cvta_generic_to_global((const void*)src)) : "memory");
}
#define CP_COMMIT() asm volatile("cp.async.commit_group;" ::: "memory")
#define CP_WAIT(n)  asm volatile("cp.async.wait_group %0;" :: "n"(n) : "memory")

__device__ __forceinline__ void ldm4(uint32_t a, uint32_t& r0, uint32_t& r1, uint32_t& r2, uint32_t& r3) {
    asm volatile("ldmatrix.sync.aligned.m8n8.x4.shared.b16 {%0,%1,%2,%3}, [%4];"
                 : "=r"(r0), "=r"(r1), "=r"(r2), "=r"(r3) : "r"(a));
}
__device__ __forceinline__ void mma16816(float* c, const uint32_t* a, const uint32_t* b) {
    asm volatile("mma.sync.aligned.m16n8k16.row.col.f32.bf16.bf16.f32 "
                 "{%0,%1,%2,%3}, {%4,%5,%6,%7}, {%8,%9}, {%0,%1,%2,%3};"
                 : "+f"(c[0]), "+f"(c[1]), "+f"(c[2]), "+f"(c[3])
                 : "r"(a[0]), "r"(a[1]), "r"(a[2]), "r"(a[3]), "r"(b[0]), "r"(b[1]));
}

__device__ __forceinline__ float gelu_f(float v) {
    float u = 0.7978845608028654f * (v + 0.044715f * v * v * v);
    return 0.5f * v * (1.0f + tanhf(u));   // jax.nn.gelu approximate=True
}

// GEMM tiling
#define BM 128
#define BN 128
#define BK 32
#define PITCHB 80                 // bytes per SMEM row (40 bf16, 16B-aligned, ldmatrix conflict-free)
#define TILEB  (BM*PITCHB)        // 10240 bytes per operand tile
#define STAGE  (4*TILEB)          // Ahi, Alo, Bhi, Blo
#define SMEM_DYN (2*STAGE)        // 81920 bytes

// ---------------- init -------------------------------------------------------------
__global__ void init_kernel() {
    if (threadIdx.x < NE) g_counts[threadIdx.x] = 0;
}

// ---------------- bf16 hi/lo split -------------------------------------------------
__global__ void __launch_bounds__(256) split_kernel(const float4* __restrict__ src,
                                                    __nv_bfloat162* __restrict__ hi,
                                                    __nv_bfloat162* __restrict__ lo,
                                                    int n4) {
    int i = blockIdx.x * blockDim.x + threadIdx.x;
    if (i >= n4) return;
    float4 v = src[i];
    __nv_bfloat16 h0 = __float2bfloat16(v.x), h1 = __float2bfloat16(v.y);
    __nv_bfloat16 h2 = __float2bfloat16(v.z), h3 = __float2bfloat16(v.w);
    hi[2*i]   = __halves2bfloat162(h0, h1);
    hi[2*i+1] = __halves2bfloat162(h2, h3);
    lo[2*i]   = __halves2bfloat162(__float2bfloat16(v.x - __bfloat162float(h0)),
                                   __float2bfloat16(v.y - __bfloat162float(h1)));
    lo[2*i+1] = __halves2bfloat162(__float2bfloat16(v.z - __bfloat162float(h2)),
                                   __float2bfloat16(v.w - __bfloat162float(h3)));
}

// ---------------- router -----------------------------------------------------------
__global__ void __launch_bounds__(256) router_kernel(const float* __restrict__ x,
                                                     const float* __restrict__ Wr)
{
    __shared__ float sP[8][16];
    const int warp = threadIdx.x >> 5;
    const int lane = threadIdx.x & 31;
    const int t = blockIdx.x * 8 + warp;

    float acc[NE];
#pragma unroll
    for (int e = 0; e < NE; e++) acc[e] = 0.f;

    const float* xr = x + (size_t)t * HD;
    for (int i = lane; i < HD; i += 32) {
        float xv = xr[i];
#pragma unroll
        for (int e = 0; e < NE; e++) acc[e] = fmaf(xv, Wr[e*HD + i], acc[e]);
    }
#pragma unroll
    for (int e = 0; e < NE; e++) {
#pragma unroll
        for (int o = 16; o > 0; o >>= 1)
            acc[e] += __shfl_xor_sync(0xffffffffu, acc[e], o);
    }
    if (lane == 0) {
        float m = acc[0];
#pragma unroll
        for (int e = 1; e < NE; e++) m = fmaxf(m, acc[e]);
        float pr[NE]; float s = 0.f;
#pragma unroll
        for (int e = 0; e < NE; e++) { pr[e] = expf(acc[e] - m); s += pr[e]; }
        float inv = 1.f / s;
#pragma unroll
        for (int e = 0; e < NE; e++) sP[warp][e] = pr[e] * inv;

        int i0 = 0; float v0 = acc[0];
#pragma unroll
        for (int e = 1; e < NE; e++) if (acc[e] > v0) { v0 = acc[e]; i0 = e; }
        float v1 = -3.4e38f; int i1 = -1;
#pragma unroll
        for (int e = 0; e < NE; e++) if (e != i0 && acc[e] > v1) { v1 = acc[e]; i1 = e; }

        float e1 = expf(v1 - v0);
        float w0 = 1.f / (1.f + e1);
        float w1 = e1 / (1.f + e1);
        g_topk_idx[2*t]   = i0;  g_topk_idx[2*t+1] = i1;
        g_topk_w[2*t]     = w0;  g_topk_w[2*t+1]   = w1;
        atomicAdd(&g_counts[i0], 1);
        atomicAdd(&g_counts[i1], 1);
    }
    __syncthreads();
    if (threadIdx.x < NE) {
        float s = 0.f;
#pragma unroll
        for (int w = 0; w < 8; w++) s += sP[w][threadIdx.x];   // fixed order: deterministic
        g_blockP[blockIdx.x * NE + threadIdx.x] = s;
    }
}

// ---------------- finalize ---------------------------------------------------------
__global__ void finalize_kernel(float* __restrict__ out, int out_size)
{
    __shared__ float part[256];
    __shared__ float sPe[NE];
    const int t = threadIdx.x;
    const int e = t & 15, c = t >> 4;
    float s = 0.f;
    for (int b = c*128; b < c*128 + 128; ++b) s += g_blockP[b*NE + e];
    part[t] = s;
    __syncthreads();
    if (t < NE) {
        float s2 = 0.f;
#pragma unroll
        for (int cc = 0; cc < 16; ++cc) s2 += part[cc*16 + t];
        sPe[t] = s2;
    }
    __syncthreads();
    if (t == 0) {
        int off = 0; float laux = 0.f;
#pragma unroll
        for (int ee = 0; ee < NE; ++ee) {
            g_offsets[ee] = off; g_cursor[ee] = off;
            int cnt = g_counts[ee];
            off += cnt;
            float f = (float)cnt * (1.0f / (float)(NTOK * TOPK));
            float P = sPe[ee]    * (1.0f / (float)NTOK);
            laux += f * P;
        }
        laux *= (float)NE;
        if (out_size > NTOK * HD) out[NTOK * HD] = laux;
    }
}

// ---------------- scatter ----------------------------------------------------------
__global__ void scatter_kernel()
{
    int t = blockIdx.x * blockDim.x + threadIdx.x;
    if (t >= NTOK) return;
#pragma unroll
    for (int j = 0; j < TOPK; j++) {
        int e = g_topk_idx[2*t + j];
        int pos = atomicAdd(&g_cursor[e], 1);
        g_pair_tok[pos] = t;
        g_pair_w[pos]   = g_topk_w[2*t + j];
    }
}

// ======================= HMMA GEMM1: h = gelu(Xg @ W1^T + b1) =====================
__global__ void __launch_bounds__(256, 1) gemm1_mma(const float* __restrict__ b1)
{
    extern __shared__ char smem[];
    const int e = blockIdx.z;
    const int count = g_counts[e];
    const int m0 = blockIdx.x * BM;
    if (m0 >= count) return;
    const int offset = g_offsets[e];
    const int n0 = blockIdx.y * BN;
    const int tid = threadIdx.x, wid = tid >> 5, lane = tid & 31;

    __shared__ int sTok[BM];
    if (tid < BM) {
        int m = m0 + tid; if (m > count - 1) m = count - 1;
        sTok[tid] = g_pair_tok[offset + m];
    }
    __syncthreads();
    const uint32_t sb = smem_u32(smem);

    // per-thread cp.async coords: 512 (row,seg) pairs, 2 per thread
    const int lrow0 = tid >> 2, lseg = tid & 3;

    // stage loader
    auto load_stage = [&](int buf, int kc) {
#pragma unroll
        for (int h = 0; h < 2; ++h) {
            int row = lrow0 + h*64;
            uint32_t d = sb + buf*STAGE + row*PITCHB + lseg*16;
            size_t ga = (size_t)sTok[row] * HD + kc + lseg*8;
            cp16(d,           g_xhi + ga);
            cp16(d + TILEB,   g_xlo + ga);
            size_t gb = ((size_t)e * FD + n0 + row) * HD + kc + lseg*8;
            cp16(d + 2*TILEB, g_w1hi + gb);
            cp16(d + 3*TILEB, g_w1lo + gb);
        }
        CP_COMMIT();
    };

    const int wm = (wid >> 2) * 64, wn = (wid & 3) * 32;
    const int lr = lane & 15, lcb = (lane >> 4) * 16;   // ldmatrix row / col-byte parts

    float acc[4][4][4];
#pragma unroll
    for (int i = 0; i < 4; i++)
#pragma unroll
        for (int j = 0; j < 4; j++)
#pragma unroll
            for (int q = 0; q < 4; q++) acc[i][j][q] = 0.f;

    const int NIT = HD / BK;   // 16
    load_stage(0, 0);
    for (int it = 0; it < NIT; ++it) {
        if (it + 1 < NIT) load_stage((it + 1) & 1, (it + 1) * BK);
        if (it + 1 < NIT) { CP_WAIT(1); } else { CP_WAIT(0); }
        __syncthreads();
        const uint32_t st = sb + (it & 1)*STAGE;
#pragma unroll
        for (int kk = 0; kk < 2; ++kk) {
            const uint32_t kb = kk*32 + lcb;
            uint32_t ah[4][4], al[4][4];
#pragma unroll
            for (int i = 0; i < 4; ++i) {
                uint32_t ra = st + (wm + i*16 + lr)*PITCHB + kb;
                ldm4(ra,          ah[i][0], ah[i][1], ah[i][2], ah[i][3]);
                ldm4(ra + TILEB,  al[i][0], al[i][1], al[i][2], al[i][3]);
            }
            uint32_t bh[4][2], bl[4][2];
#pragma unroll
            for (int jj = 0; jj < 2; ++jj) {
                uint32_t rb = st + 2*TILEB + (wn + jj*16 + lr)*PITCHB + kb;
                uint32_t r0, r1, r2, r3;
                ldm4(rb, r0, r1, r2, r3);
                bh[2*jj][0] = r0; bh[2*jj+1][0] = r1; bh[2*jj][1] = r2; bh[2*jj+1][1] = r3;
                ldm4(rb + TILEB, r0, r1, r2, r3);
                bl[2*jj][0] = r0; bl[2*jj+1][0] = r1; bl[2*jj][1] = r2; bl[2*jj+1][1] = r3;
            }
#pragma unroll
            for (int i = 0; i < 4; ++i)
#pragma unroll
                for (int j = 0; j < 4; ++j) {
                    mma16816(acc[i][j], ah[i], bh[j]);
                    mma16816(acc[i][j], ah[i], bl[j]);
                    mma16816(acc[i][j], al[i], bh[j]);
                }
        }
        __syncthreads();
    }

    // epilogue: bias + gelu + bf16 hi/lo split store
#pragma unroll
    for (int i = 0; i < 4; ++i) {
#pragma unroll
        for (int j = 0; j < 4; ++j) {
            int col = n0 + wn + j*8 + (lane & 3)*2;
            float bb0 = __ldg(&b1[e*FD + col]);
            float bb1 = __ldg(&b1[e*FD + col + 1]);
#pragma unroll
            for (int half = 0; half < 2; ++half) {
                int m  = wm + i*16 + (lane >> 2) + half*8;
                int gm = m0 + m;
                if (gm < count) {
                    float v0 = gelu_f(acc[i][j][half*2]     + bb0);
                    float v1 = gelu_f(acc[i][j][half*2 + 1] + bb1);
                    __nv_bfloat16 h0 = __float2bfloat16(v0), h1 = __float2bfloat16(v1);
                    __nv_bfloat16 l0 = __float2bfloat16(v0 - __bfloat162float(h0));
                    __nv_bfloat16 l1 = __float2bfloat16(v1 - __bfloat162float(h1));
                    size_t o = (size_t)(offset + gm) * FD + col;
                    *(__nv_bfloat162*)(g_hhi + o) = __halves2bfloat162(h0, h1);
                    *(__nv_bfloat162*)(g_hlo + o) = __halves2bfloat162(l0, l1);
                }
            }
        }
    }
}

// ======================= HMMA GEMM2: y += w * (h @ W2^T + b2) =====================
__global__ void __launch_bounds__(256, 1) gemm2_mma(const float* __restrict__ b2,
                                                    float* __restrict__ y)
{
    extern __shared__ char smem[];
    const int e = blockIdx.z;
    const int count = g_counts[e];
    const int m0 = blockIdx.x * BM;
    if (m0 >= count) return;
    const int offset = g_offsets[e];
    const int n0 = blockIdx.y * BN;
    const int tid = threadIdx.x, wid = tid >> 5, lane = tid & 31;

    __shared__ int   sTok[BM];
    __shared__ float sW[BM];
    if (tid < BM) {
        int m = m0 + tid; if (m > count - 1) m = count - 1;
        sTok[tid] = g_pair_tok[offset + m];
        sW[tid]   = g_pair_w[offset + m];
    }
    __syncthreads();
    const uint32_t sb = smem_u32(smem);

    const int lrow0 = tid >> 2, lseg = tid & 3;

    auto load_stage = [&](int buf, int kc) {
#pragma unroll
        for (int h = 0; h < 2; ++h) {
            int row = lrow0 + h*64;
            uint32_t d = sb + buf*STAGE + row*PITCHB + lseg*16;
            int r = m0 + row; if (r > count - 1) r = count - 1;
            size_t ga = (size_t)(offset + r) * FD + kc + lseg*8;
            cp16(d,           g_hhi + ga);
            cp16(d + TILEB,   g_hlo + ga);
            size_t gb = ((size_t)e * HD + n0 + row) * FD + kc + lseg*8;
            cp16(d + 2*TILEB, g_w2hi + gb);
            cp16(d + 3*TILEB, g_w2lo + gb);
        }
        CP_COMMIT();
    };

    const int wm = (wid >> 2) * 64, wn = (wid & 3) * 32;
    const int lr = lane & 15, lcb = (lane >> 4) * 16;

    float acc[4][4][4];
#pragma unroll
    for (int i = 0; i < 4; i++)
#pragma unroll
        for (int j = 0; j < 4; j++)
#pragma unroll
            for (int q = 0; q < 4; q++) acc[i][j][q] = 0.f;

    const int NIT = FD / BK;   // 32
    load_stage(0, 0);
    for (int it = 0; it < NIT; ++it) {
        if (it + 1 < NIT) load_stage((it + 1) & 1, (it + 1) * BK);
        if (it + 1 < NIT) { CP_WAIT(1); } else { CP_WAIT(0); }
        __syncthreads();
        const uint32_t st = sb + (it & 1)*STAGE;
#pragma unroll
        for (int kk = 0; kk < 2; ++kk) {
            const uint32_t kb = kk*32 + lcb;
            uint32_t ah[4][4], al[4][4];
#pragma unroll
            for (int i = 0; i < 4; ++i) {
                uint32_t ra = st + (wm + i*16 + lr)*PITCHB + kb;
                ldm4(ra,          ah[i][0], ah[i][1], ah[i][2], ah[i][3]);
                ldm4(ra + TILEB,  al[i][0], al[i][1], al[i][2], al[i][3]);
            }
            uint32_t bh[4][2], bl[4][2];
#pragma unroll
            for (int jj = 0; jj < 2; ++jj) {
                uint32_t rb = st + 2*TILEB + (wn + jj*16 + lr)*PITCHB + kb;
                uint32_t r0, r1, r2, r3;
                ldm4(rb, r0, r1, r2, r3);
                bh[2*jj][0] = r0; bh[2*jj+1][0] = r1; bh[2*jj][1] = r2; bh[2*jj+1][1] = r3;
                ldm4(rb + TILEB, r0, r1, r2, r3);
                bl[2*jj][0] = r0; bl[2*jj+1][0] = r1; bl[2*jj][1] = r2; bl[2*jj+1][1] = r3;
            }
#pragma unroll
            for (int i = 0; i < 4; ++i)
#pragma unroll
                for (int j = 0; j < 4; ++j) {
                    mma16816(acc[i][j], ah[i], bh[j]);
                    mma16816(acc[i][j], ah[i], bl[j]);
                    mma16816(acc[i][j], al[i], bh[j]);
                }
        }
        __syncthreads();
    }

    // epilogue: weighted atomic accumulate into y
#pragma unroll
    for (int i = 0; i < 4; ++i) {
#pragma unroll
        for (int j = 0; j < 4; ++j) {
            int col = n0 + wn + j*8 + (lane & 3)*2;
            float bb0 = __ldg(&b2[e*HD + col]);
            float bb1 = __ldg(&b2[e*HD + col + 1]);
#pragma unroll
            for (int half = 0; half < 2; ++half) {
                int m  = wm + i*16 + (lane >> 2) + half*8;
                int gm = m0 + m;
                if (gm < count) {
                    int   tok = sTok[m];
                    float w   = sW[m];
                    float* dst = y + (size_t)tok * HD + col;
                    atomicAdd(&dst[0], w * (acc[i][j][half*2]     + bb0));
                    atomicAdd(&dst[1], w * (acc[i][j][half*2 + 1] + bb1));
                }
            }
        }
    }
}

// ---------------- launch -----------------------------------------------------------
extern "C" void kernel_launch(void* const* d_in, const int* in_sizes, int n_in,
                              void* d_out, int out_size)
{
    const float* x  = (const float*)d_in[0];
    const float* Wr = (const float*)d_in[1];
    const float* W1 = (const float*)d_in[2];
    const float* b1 = (const float*)d_in[3];
    const float* W2 = (const float*)d_in[4];
    const float* b2 = (const float*)d_in[5];
    float* y = (float*)d_out;

    cudaFuncSetAttribute(gemm1_mma, cudaFuncAttributeMaxDynamicSharedMemorySize, SMEM_DYN);
    cudaFuncSetAttribute(gemm2_mma, cudaFuncAttributeMaxDynamicSharedMemorySize, SMEM_DYN);

    cudaMemsetAsync(d_out, 0, (size_t)out_size * sizeof(float));
    init_kernel<<<1, 32>>>();

    {
        __nv_bfloat162 *xhi, *xlo, *w1hi, *w1lo, *w2hi, *w2lo;
        cudaGetSymbolAddress((void**)&xhi,  g_xhi);
        cudaGetSymbolAddress((void**)&xlo,  g_xlo);
        cudaGetSymbolAddress((void**)&w1hi, g_w1hi);
        cudaGetSymbolAddress((void**)&w1lo, g_w1lo);
        cudaGetSymbolAddress((void**)&w2hi, g_w2hi);
        cudaGetSymbolAddress((void**)&w2lo, g_w2lo);
        const int n4 = (NTOK*HD)/4;
        split_kernel<<<n4/256, 256>>>((const float4*)x,  xhi,  xlo,  n4);
        split_kernel<<<n4/256, 256>>>((const float4*)W1, w1hi, w1lo, n4);
        split_kernel<<<n4/256, 256>>>((const float4*)W2, w2hi, w2lo, n4);
    }

    router_kernel<<<RB, 256>>>(x, Wr);
    finalize_kernel<<<1, 256>>>(y, out_size);
    scatter_kernel<<<64, 256>>>();

    gemm1_mma<<<dim3(NTOK/128, FD/128, NE), 256, SMEM_DYN>>>(b1);
    gemm2_mma<<<dim3(NTOK/128, HD/128, NE), 256, SMEM_DYN>>>(b2, y);
}

// round 4
// speedup vs baseline: 3.3824x; 2.0116x over previous
#include <cuda_runtime.h>
#include <cuda_bf16.h>
#include <cuda_fp16.h>
#include <math.h>
#include <stdint.h>

#define NTOK 16384      // B*S
#define HD   512
#define FD   1024
#define NE   16
#define TOPK 2
#define RB   2048       // router blocks (8 tokens each)
#define NPAIR (NTOK*TOPK)

// ---------------- scratch (static device globals; no allocation) ----------------
__device__ int   g_counts[NE];
__device__ int   g_offsets[NE];
__device__ int   g_cursor[NE];
__device__ float g_blockP[RB*NE];
__device__ int   g_topk_idx[NPAIR];
__device__ float g_topk_w[NPAIR];
__device__ int   g_pair_tok[NPAIR];
__device__ float g_pair_w[NPAIR];

// fp16 copies
__device__ __half g_xh[NTOK*HD];
__device__ __half g_w1h[NE*FD*HD];
__device__ __half g_w2h[NE*HD*FD];
__device__ __half g_h[(size_t)NPAIR*FD];     // intermediate h (fp16), 67 MB

// ---------------- helpers ---------------------------------------------------------
__device__ __forceinline__ uint32_t smem_u32(const void* p) {
    uint32_t a;
    asm("{ .reg .u64 t; cvta.to.shared.u64 t, %1; cvt.u32.u64 %0, t; }" : "=r"(a) : "l"(p));
    return a;
}
__device__ __forceinline__ void cp16(uint32_t dst, const __half* src) {
    asm volatile("cp.async.cg.shared.global [%0], [%1], 16;"
                 :: "r"(dst), "l"(__cvta_generic_to_global((const void*)src)) : "memory");
}
#define CP_COMMIT() asm volatile("cp.async.commit_group;" ::: "memory")
#define CP_WAIT(n)  asm volatile("cp.async.wait_group %0;" :: "n"(n) : "memory")

__device__ __forceinline__ void ldm4(uint32_t a, uint32_t& r0, uint32_t& r1, uint32_t& r2, uint32_t& r3) {
    asm volatile("ldmatrix.sync.aligned.m8n8.x4.shared.b16 {%0,%1,%2,%3}, [%4];"
                 : "=r"(r0), "=r"(r1), "=r"(r2), "=r"(r3) : "r"(a));
}
__device__ __forceinline__ void mma16816(float* c, const uint32_t* a, const uint32_t* b) {
    asm volatile("mma.sync.aligned.m16n8k16.row.col.f32.f16.f16.f32 "
                 "{%0,%1,%2,%3}, {%4,%5,%6,%7}, {%8,%9}, {%0,%1,%2,%3};"
                 : "+f"(c[0]), "+f"(c[1]), "+f"(c[2]), "+f"(c[3])
                 : "r"(a[0]), "r"(a[1]), "r"(a[2]), "r"(a[3]), "r"(b[0]), "r"(b[1]));
}

__device__ __forceinline__ float gelu_f(float v) {
    float u = 0.7978845608028654f * (v + 0.044715f * v * v * v);
    return 0.5f * v * (1.0f + tanhf(u));   // jax.nn.gelu approximate=True
}

// GEMM tiling: 128x128 CTA, BK=64, 8 warps (2x4), 64x32 warp tile, 3-stage cp.async
#define BM 128
#define BN 128
#define BK 64
#define PITCH 144                 // 128B data + 16B pad (ldmatrix conflict-free)
#define TILEB  (BM*PITCH)         // 18432
#define STAGE  (2*TILEB)          // A + B = 36864
#define NSTAGE 3
#define SMEM_DYN (NSTAGE*STAGE)   // 110592

// ---------------- init -------------------------------------------------------------
__global__ void init_kernel() {
    if (threadIdx.x < NE) g_counts[threadIdx.x] = 0;
}

// ---------------- fp32 -> fp16 convert ---------------------------------------------
__global__ void __launch_bounds__(256) split_kernel(const float4* __restrict__ src,
                                                    __half2* __restrict__ dst, int n4) {
    int i = blockIdx.x * blockDim.x + threadIdx.x;
    if (i >= n4) return;
    float4 v = src[i];
    dst[2*i]   = __floats2half2_rn(v.x, v.y);
    dst[2*i+1] = __floats2half2_rn(v.z, v.w);
}

// ---------------- router -----------------------------------------------------------
__global__ void __launch_bounds__(256) router_kernel(const float* __restrict__ x,
                                                     const float* __restrict__ Wr)
{
    __shared__ float sP[8][16];
    const int warp = threadIdx.x >> 5;
    const int lane = threadIdx.x & 31;
    const int t = blockIdx.x * 8 + warp;

    float acc[NE];
#pragma unroll
    for (int e = 0; e < NE; e++) acc[e] = 0.f;

    const float* xr = x + (size_t)t * HD;
    for (int i = lane; i < HD; i += 32) {
        float xv = xr[i];
#pragma unroll
        for (int e = 0; e < NE; e++) acc[e] = fmaf(xv, Wr[e*HD + i], acc[e]);
    }
#pragma unroll
    for (int e = 0; e < NE; e++) {
#pragma unroll
        for (int o = 16; o > 0; o >>= 1)
            acc[e] += __shfl_xor_sync(0xffffffffu, acc[e], o);
    }
    if (lane == 0) {
        float m = acc[0];
#pragma unroll
        for (int e = 1; e < NE; e++) m = fmaxf(m, acc[e]);
        float pr[NE]; float s = 0.f;
#pragma unroll
        for (int e = 0; e < NE; e++) { pr[e] = expf(acc[e] - m); s += pr[e]; }
        float inv = 1.f / s;
#pragma unroll
        for (int e = 0; e < NE; e++) sP[warp][e] = pr[e] * inv;

        int i0 = 0; float v0 = acc[0];
#pragma unroll
        for (int e = 1; e < NE; e++) if (acc[e] > v0) { v0 = acc[e]; i0 = e; }
        float v1 = -3.4e38f; int i1 = -1;
#pragma unroll
        for (int e = 0; e < NE; e++) if (e != i0 && acc[e] > v1) { v1 = acc[e]; i1 = e; }

        float e1 = expf(v1 - v0);
        float w0 = 1.f / (1.f + e1);
        float w1 = e1 / (1.f + e1);
        g_topk_idx[2*t]   = i0;  g_topk_idx[2*t+1] = i1;
        g_topk_w[2*t]     = w0;  g_topk_w[2*t+1]   = w1;
        atomicAdd(&g_counts[i0], 1);
        atomicAdd(&g_counts[i1], 1);
    }
    __syncthreads();
    if (threadIdx.x < NE) {
        float s = 0.f;
#pragma unroll
        for (int w = 0; w < 8; w++) s += sP[w][threadIdx.x];   // fixed order: deterministic
        g_blockP[blockIdx.x * NE + threadIdx.x] = s;
    }
}

// ---------------- finalize ---------------------------------------------------------
__global__ void finalize_kernel(float* __restrict__ out, int out_size)
{
    __shared__ float part[256];
    __shared__ float sPe[NE];
    const int t = threadIdx.x;
    const int e = t & 15, c = t >> 4;
    float s = 0.f;
    for (int b = c*128; b < c*128 + 128; ++b) s += g_blockP[b*NE + e];
    part[t] = s;
    __syncthreads();
    if (t < NE) {
        float s2 = 0.f;
#pragma unroll
        for (int cc = 0; cc < 16; ++cc) s2 += part[cc*16 + t];
        sPe[t] = s2;
    }
    __syncthreads();
    if (t == 0) {
        int off = 0; float laux = 0.f;
#pragma unroll
        for (int ee = 0; ee < NE; ++ee) {
            g_offsets[ee] = off; g_cursor[ee] = off;
            int cnt = g_counts[ee];
            off += cnt;
            float f = (float)cnt * (1.0f / (float)(NTOK * TOPK));
            float P = sPe[ee]    * (1.0f / (float)NTOK);
            laux += f * P;
        }
        laux *= (float)NE;
        if (out_size > NTOK * HD) out[NTOK * HD] = laux;
    }
}

// ---------------- scatter ----------------------------------------------------------
__global__ void scatter_kernel()
{
    int t = blockIdx.x * blockDim.x + threadIdx.x;
    if (t >= NTOK) return;
#pragma unroll
    for (int j = 0; j < TOPK; j++) {
        int e = g_topk_idx[2*t + j];
        int pos = atomicAdd(&g_cursor[e], 1);
        g_pair_tok[pos] = t;
        g_pair_w[pos]   = g_topk_w[2*t + j];
    }
}

// ======================= HMMA GEMM1: h = gelu(Xg @ W1^T + b1) =====================
__global__ void __launch_bounds__(256, 1) gemm1_mma(const float* __restrict__ b1)
{
    extern __shared__ char smem[];
    const int e = blockIdx.z;
    const int count = g_counts[e];
    const int m0 = blockIdx.x * BM;
    if (m0 >= count) return;
    const int offset = g_offsets[e];
    const int n0 = blockIdx.y * BN;
    const int tid = threadIdx.x, wid = tid >> 5, lane = tid & 31;

    __shared__ int sTok[BM];
    if (tid < BM) {
        int m = m0 + tid; if (m > count - 1) m = count - 1;
        sTok[tid] = g_pair_tok[offset + m];
    }
    __syncthreads();
    const uint32_t sb = smem_u32(smem);

    const int lrow = tid >> 1, lsg = (tid & 1) * 4;   // row + 4-seg group per thread

    auto load_stage = [&](int buf, int kc) {
        uint32_t base = sb + buf*STAGE;
        {
            size_t ga = (size_t)sTok[lrow] * HD + kc + lsg*8;
            uint32_t d = base + lrow*PITCH + lsg*16;
            cp16(d, g_xh+ga); cp16(d+16, g_xh+ga+8); cp16(d+32, g_xh+ga+16); cp16(d+48, g_xh+ga+24);
        }
        {
            size_t gb = ((size_t)e * FD + n0 + lrow) * HD + kc + lsg*8;
            uint32_t d = base + TILEB + lrow*PITCH + lsg*16;
            cp16(d, g_w1h+gb); cp16(d+16, g_w1h+gb+8); cp16(d+32, g_w1h+gb+16); cp16(d+48, g_w1h+gb+24);
        }
        CP_COMMIT();
    };

    const int wm = (wid >> 2) * 64, wn = (wid & 3) * 32;
    const int lr = lane & 15, lcb = (lane >> 4) * 16;

    float acc[4][4][4];
#pragma unroll
    for (int i = 0; i < 4; i++)
#pragma unroll
        for (int j = 0; j < 4; j++)
#pragma unroll
            for (int q = 0; q < 4; q++) acc[i][j][q] = 0.f;

    const int NIT = HD / BK;   // 8
    load_stage(0, 0); load_stage(1, BK); load_stage(2, 2*BK);
    for (int it = 0; it < NIT; ++it) {
        CP_WAIT(2);
        __syncthreads();
        const uint32_t st = sb + (it % 3)*STAGE;
#pragma unroll
        for (int kk = 0; kk < 4; ++kk) {
            const uint32_t kb = kk*32 + lcb;
            uint32_t a[4][4];
#pragma unroll
            for (int i = 0; i < 4; ++i)
                ldm4(st + (wm + i*16 + lr)*PITCH + kb, a[i][0], a[i][1], a[i][2], a[i][3]);
            uint32_t b[4][2];
#pragma unroll
            for (int jj = 0; jj < 2; ++jj) {
                uint32_t r0, r1, r2, r3;
                ldm4(st + TILEB + (wn + jj*16 + lr)*PITCH + kb, r0, r1, r2, r3);
                b[2*jj][0] = r0; b[2*jj+1][0] = r1; b[2*jj][1] = r2; b[2*jj+1][1] = r3;
            }
#pragma unroll
            for (int i = 0; i < 4; ++i)
#pragma unroll
                for (int j = 0; j < 4; ++j)
                    mma16816(acc[i][j], a[i], b[j]);
        }
        __syncthreads();
        if (it + 3 < NIT) load_stage(it % 3, (it + 3) * BK); else CP_COMMIT();
    }

    // epilogue: bias + gelu + fp16 store
#pragma unroll
    for (int i = 0; i < 4; ++i) {
#pragma unroll
        for (int j = 0; j < 4; ++j) {
            int col = n0 + wn + j*8 + (lane & 3)*2;
            float bb0 = __ldg(&b1[e*FD + col]);
            float bb1 = __ldg(&b1[e*FD + col + 1]);
#pragma unroll
            for (int half = 0; half < 2; ++half) {
                int m  = wm + i*16 + (lane >> 2) + half*8;
                int gm = m0 + m;
                if (gm < count) {
                    float v0 = gelu_f(acc[i][j][half*2]     + bb0);
                    float v1 = gelu_f(acc[i][j][half*2 + 1] + bb1);
                    size_t o = (size_t)(offset + gm) * FD + col;
                    *(__half2*)(g_h + o) = __floats2half2_rn(v0, v1);
                }
            }
        }
    }
}

// ======================= HMMA GEMM2: y += w * (h @ W2^T + b2) =====================
__global__ void __launch_bounds__(256, 1) gemm2_mma(const float* __restrict__ b2,
                                                    float* __restrict__ y)
{
    extern __shared__ char smem[];
    const int e = blockIdx.z;
    const int count = g_counts[e];
    const int m0 = blockIdx.x * BM;
    if (m0 >= count) return;
    const int offset = g_offsets[e];
    const int n0 = blockIdx.y * BN;
    const int tid = threadIdx.x, wid = tid >> 5, lane = tid & 31;

    __shared__ int   sTok[BM];
    __shared__ float sW[BM];
    if (tid < BM) {
        int m = m0 + tid; if (m > count - 1) m = count - 1;
        sTok[tid] = g_pair_tok[offset + m];
        sW[tid]   = g_pair_w[offset + m];
    }
    __syncthreads();
    const uint32_t sb = smem_u32(smem);

    const int lrow = tid >> 1, lsg = (tid & 1) * 4;
    int ar = m0 + lrow; if (ar > count - 1) ar = count - 1;
    const size_t arow = (size_t)(offset + ar) * FD;

    auto load_stage = [&](int buf, int kc) {
        uint32_t base = sb + buf*STAGE;
        {
            size_t ga = arow + kc + lsg*8;
            uint32_t d = base + lrow*PITCH + lsg*16;
            cp16(d, g_h+ga); cp16(d+16, g_h+ga+8); cp16(d+32, g_h+ga+16); cp16(d+48, g_h+ga+24);
        }
        {
            size_t gb = ((size_t)e * HD + n0 + lrow) * FD + kc + lsg*8;
            uint32_t d = base + TILEB + lrow*PITCH + lsg*16;
            cp16(d, g_w2h+gb); cp16(d+16, g_w2h+gb+8); cp16(d+32, g_w2h+gb+16); cp16(d+48, g_w2h+gb+24);
        }
        CP_COMMIT();
    };

    const int wm = (wid >> 2) * 64, wn = (wid & 3) * 32;
    const int lr = lane & 15, lcb = (lane >> 4) * 16;

    float acc[4][4][4];
#pragma unroll
    for (int i = 0; i < 4; i++)
#pragma unroll
        for (int j = 0; j < 4; j++)
#pragma unroll
            for (int q = 0; q < 4; q++) acc[i][j][q] = 0.f;

    const int NIT = FD / BK;   // 16
    load_stage(0, 0); load_stage(1, BK); load_stage(2, 2*BK);
    for (int it = 0; it < NIT; ++it) {
        CP_WAIT(2);
        __syncthreads();
        const uint32_t st = sb + (it % 3)*STAGE;
#pragma unroll
        for (int kk = 0; kk < 4; ++kk) {
            const uint32_t kb = kk*32 + lcb;
            uint32_t a[4][4];
#pragma unroll
            for (int i = 0; i < 4; ++i)
                ldm4(st + (wm + i*16 + lr)*PITCH + kb, a[i][0], a[i][1], a[i][2], a[i][3]);
            uint32_t b[4][2];
#pragma unroll
            for (int jj = 0; jj < 2; ++jj) {
                uint32_t r0, r1, r2, r3;
                ldm4(st + TILEB + (wn + jj*16 + lr)*PITCH + kb, r0, r1, r2, r3);
                b[2*jj][0] = r0; b[2*jj+1][0] = r1; b[2*jj][1] = r2; b[2*jj+1][1] = r3;
            }
#pragma unroll
            for (int i = 0; i < 4; ++i)
#pragma unroll
                for (int j = 0; j < 4; ++j)
                    mma16816(acc[i][j], a[i], b[j]);
        }
        __syncthreads();
        if (it + 3 < NIT) load_stage(it % 3, (it + 3) * BK); else CP_COMMIT();
    }

    // epilogue: weighted atomic accumulate into y
#pragma unroll
    for (int i = 0; i < 4; ++i) {
#pragma unroll
        for (int j = 0; j < 4; ++j) {
            int col = n0 + wn + j*8 + (lane & 3)*2;
            float bb0 = __ldg(&b2[e*HD + col]);
            float bb1 = __ldg(&b2[e*HD + col + 1]);
#pragma unroll
            for (int half = 0; half < 2; ++half) {
                int m  = wm + i*16 + (lane >> 2) + half*8;
                int gm = m0 + m;
                if (gm < count) {
                    int   tok = sTok[m];
                    float w   = sW[m];
                    float* dst = y + (size_t)tok * HD + col;
                    atomicAdd(&dst[0], w * (acc[i][j][half*2]     + bb0));
                    atomicAdd(&dst[1], w * (acc[i][j][half*2 + 1] + bb1));
                }
            }
        }
    }
}

// ---------------- launch -----------------------------------------------------------
extern "C" void kernel_launch(void* const* d_in, const int* in_sizes, int n_in,
                              void* d_out, int out_size)
{
    const float* x  = (const float*)d_in[0];
    const float* Wr = (const float*)d_in[1];
    const float* W1 = (const float*)d_in[2];
    const float* b1 = (const float*)d_in[3];
    const float* W2 = (const float*)d_in[4];
    const float* b2 = (const float*)d_in[5];
    float* y = (float*)d_out;

    cudaFuncSetAttribute(gemm1_mma, cudaFuncAttributeMaxDynamicSharedMemorySize, SMEM_DYN);
    cudaFuncSetAttribute(gemm2_mma, cudaFuncAttributeMaxDynamicSharedMemorySize, SMEM_DYN);

    cudaMemsetAsync(d_out, 0, (size_t)out_size * sizeof(float));
    init_kernel<<<1, 32>>>();

    {
        __half2 *xh, *w1h, *w2h;
        cudaGetSymbolAddress((void**)&xh,  g_xh);
        cudaGetSymbolAddress((void**)&w1h, g_w1h);
        cudaGetSymbolAddress((void**)&w2h, g_w2h);
        const int n4 = (NTOK*HD)/4;
        split_kernel<<<n4/256, 256>>>((const float4*)x,  xh,  n4);
        split_kernel<<<n4/256, 256>>>((const float4*)W1, w1h, n4);
        split_kernel<<<n4/256, 256>>>((const float4*)W2, w2h, n4);
    }

    router_kernel<<<RB, 256>>>(x, Wr);
    finalize_kernel<<<1, 256>>>(y, out_size);
    scatter_kernel<<<64, 256>>>();

    gemm1_mma<<<dim3(NTOK/128, FD/128, NE), 256, SMEM_DYN>>>(b1);
    gemm2_mma<<<dim3(NTOK/128, HD/128, NE), 256, SMEM_DYN>>>(b2, y);
}